// round 13
// baseline (speedup 1.0000x reference)
#include <cuda_runtime.h>
#include <cstdint>

// Scratch: 4 channel-groups, each acc_g[k*16 + cc] packed
// (sortable_value:32 | (N-j):32). Group footprint = N*16*8B = 64MB (L2-resident).
__device__ unsigned long long g_acc[32000000];

__device__ __forceinline__ unsigned f2sort(float f) {
    unsigned u = __float_as_uint(f);
    return (u & 0x80000000u) ? ~u : (u | 0x80000000u);
}
__device__ __forceinline__ float sort2f(unsigned s) {
    unsigned u = (s & 0x80000000u) ? (s ^ 0x80000000u) : ~s;
    return __uint_as_float(u);
}

// -------------------- Pass 1: scatter, one channel-group (16 ch) --------------------
__global__ void scatter16_kernel(const float* __restrict__ src,
                                 const int* __restrict__ index,
                                 int N, int c0,
                                 unsigned long long* __restrict__ acc) {
    int t    = threadIdx.x;
    int half = t & 1;
    int g    = t >> 1;
    int j0   = blockIdx.x * 512 + g * 4;
    if (j0 >= N) return;
    int ch0 = c0 + half * 8;
    int cc0 = half * 8;

    if (j0 + 4 <= N) {
        int4 idx4 = __ldcs(reinterpret_cast<const int4*>(index + j0));
        float4 v[8];
#pragma unroll
        for (int c = 0; c < 8; ++c)
            v[c] = __ldcs(reinterpret_cast<const float4*>(
                src + (size_t)(ch0 + c) * N + j0));

        int kk[4] = {idx4.x, idx4.y, idx4.z, idx4.w};
#pragma unroll
        for (int i = 0; i < 4; ++i) {
            unsigned long long lowkey = (unsigned)(N - (j0 + i));
            unsigned long long* ap = acc + (size_t)kk[i] * 16 + cc0;
#pragma unroll
            for (int c = 0; c < 8; ++c) {
                float fv = (i == 0) ? v[c].x : (i == 1) ? v[c].y
                                             : (i == 2) ? v[c].z : v[c].w;
                unsigned long long p =
                    ((unsigned long long)f2sort(fv) << 32) | lowkey;
                atomicMax(ap + c, p);
            }
        }
    } else {
        for (int i = 0; i < 4 && j0 + i < N; ++i) {
            int j = j0 + i;
            int k = __ldcs(index + j);
            unsigned long long lowkey = (unsigned)(N - j);
            unsigned long long* ap = acc + (size_t)k * 16 + cc0;
#pragma unroll
            for (int c = 0; c < 8; ++c) {
                float fv = __ldcs(src + (size_t)(ch0 + c) * N + j);
                unsigned long long p =
                    ((unsigned long long)f2sort(fv) << 32) | lowkey;
                atomicMax(ap + c, p);
            }
        }
    }
}

// -------------------- Pass 2: per-group finalize (16 channels) --------------------
__global__ void finalize16_kernel(const float* __restrict__ src,
                                  float* __restrict__ out,
                                  float* __restrict__ arg,
                                  int N, int writeArg, int c0,
                                  const unsigned long long* __restrict__ acc) {
    __shared__ __align__(16) float s_val[16][68];
    __shared__ __align__(16) float s_arg[16][68];
    int k0  = blockIdx.x * 64;
    int tid = threadIdx.x;

    if (k0 + 64 <= N) {
        const longlong2* accv =
            reinterpret_cast<const longlong2*>(acc + (size_t)k0 * 16);
#pragma unroll
        for (int i = 0; i < 2; ++i) {
            int idx2 = i * 256 + tid;          // 0..511 ll2 in tile
            longlong2 p2 = __ldcs(accv + idx2);
            int e  = idx2 * 2;                  // element index kk*16+cc
            int kk = e >> 4;
            int cc = e & 15;
            {
                unsigned long long p = (unsigned long long)p2.x;
                unsigned low = (unsigned)p, hi = (unsigned)(p >> 32);
                s_val[cc][kk] = low ? sort2f(hi) : __int_as_float(0xff800000);
                s_arg[cc][kk] = (float)(low ? (N - (int)low) : N);
            }
            {
                unsigned long long p = (unsigned long long)p2.y;
                unsigned low = (unsigned)p, hi = (unsigned)(p >> 32);
                s_val[cc + 1][kk] = low ? sort2f(hi) : __int_as_float(0xff800000);
                s_arg[cc + 1][kk] = (float)(low ? (N - (int)low) : N);
            }
        }
        __syncthreads();

        float fN = (float)N;
        int c  = tid >> 4;            // 0..15
        int kk = (tid & 15) * 4;      // 0..60
        size_t gidx = (size_t)(c0 + c) * N + (k0 + kk);
        float4 sv = __ldcs(reinterpret_cast<const float4*>(src + gidx));
        float4 sg = *reinterpret_cast<const float4*>(&s_val[c][kk]);
        float4 sa = *reinterpret_cast<const float4*>(&s_arg[c][kk]);
        float4 ov, av;
        ov.x = fmaxf(sv.x, sg.x); av.x = (sg.x >= sv.x) ? sa.x : fN;
        ov.y = fmaxf(sv.y, sg.y); av.y = (sg.y >= sv.y) ? sa.y : fN;
        ov.z = fmaxf(sv.z, sg.z); av.z = (sg.z >= sv.z) ? sa.z : fN;
        ov.w = fmaxf(sv.w, sg.w); av.w = (sg.w >= sv.w) ? sa.w : fN;
        __stcs(reinterpret_cast<float4*>(out + gidx), ov);
        if (writeArg) __stcs(reinterpret_cast<float4*>(arg + gidx), av);
    } else {
        for (int e = tid; e < 64 * 16; e += blockDim.x) {
            int kk = e >> 4;
            int cc = e & 15;
            int k  = k0 + kk;
            float val = __int_as_float(0xff800000);
            int a = N;
            if (k < N) {
                unsigned long long p = acc[(size_t)k * 16 + cc];
                unsigned low = (unsigned)p, hi = (unsigned)(p >> 32);
                if (low) { val = sort2f(hi); a = N - (int)low; }
            }
            s_val[cc][kk] = val;
            s_arg[cc][kk] = (float)a;
        }
        __syncthreads();
        for (int e = tid; e < 16 * 64; e += blockDim.x) {
            int c  = e >> 6;
            int kk = e & 63;
            int k  = k0 + kk;
            if (k < N) {
                size_t idx = (size_t)(c0 + c) * N + k;
                float sv  = src[idx];
                float seg = s_val[c][kk];
                out[idx] = fmaxf(sv, seg);
                if (writeArg) arg[idx] = (seg >= sv) ? s_arg[c][kk] : (float)N;
            }
        }
    }
}

// -------------------- Generic fallback (C != 64) --------------------
__global__ void scatter_gen_kernel(const float* __restrict__ src,
                                   const int* __restrict__ index,
                                   int C, int N) {
    int j = blockIdx.x * blockDim.x + threadIdx.x;
    if (j >= N) return;
    int k = index[j];
    unsigned long long* accp = g_acc + (size_t)k * C;
    unsigned lowkey = (unsigned)(N - j);
    for (int c = 0; c < C; ++c) {
        float v = __ldg(src + (size_t)c * N + j);
        unsigned long long p =
            ((unsigned long long)f2sort(v) << 32) | (unsigned long long)lowkey;
        atomicMax(accp + c, p);
    }
}

__global__ void finalize_gen_kernel(const float* __restrict__ src,
                                    float* __restrict__ out,
                                    float* __restrict__ arg,
                                    int C, int N, int writeArg) {
    long long t = (long long)blockIdx.x * blockDim.x + threadIdx.x;
    long long total = (long long)C * N;
    if (t >= total) return;
    int c = (int)(t / N);
    int k = (int)(t % N);
    unsigned long long p = g_acc[(size_t)k * C + c];
    unsigned low = (unsigned)p, hi = (unsigned)(p >> 32);
    float seg = low ? sort2f(hi) : __int_as_float(0xff800000);
    int   a   = low ? (N - (int)low) : N;
    float sv = src[t];
    out[t] = fmaxf(sv, seg);
    if (writeArg) arg[t] = (float)((seg >= sv) ? a : N);
}

extern "C" void kernel_launch(void* const* d_in, const int* in_sizes, int n_in,
                              void* d_out, int out_size) {
    const float* src   = (const float*)d_in[0];
    const int*   index = (const int*)d_in[1];   // JAX x64-disabled: int32

    int N = in_sizes[1];
    int C = (N > 0) ? (in_sizes[0] / N) : 0;
    if (N <= 0 || C <= 0) return;

    size_t cn = (size_t)C * (size_t)N;

    unsigned char* accp = nullptr;
    cudaGetSymbolAddress((void**)&accp, g_acc);

    float* out = (float*)d_out;
    int writeArg = ((size_t)out_size >= 2 * cn) ? 1 : 0;
    float* arg = out + cn;

    if (C == 64) {
        static bool s_init = false;
        static cudaStream_t s1, s2;
        static cudaEvent_t evRoot, evM[4], evPre[4], evS[4], evJ;
        if (!s_init) {
            cudaStreamCreateWithFlags(&s1, cudaStreamNonBlocking);
            cudaStreamCreateWithFlags(&s2, cudaStreamNonBlocking);
            cudaEventCreateWithFlags(&evRoot, cudaEventDisableTiming);
            for (int i = 0; i < 4; ++i) {
                cudaEventCreateWithFlags(&evM[i], cudaEventDisableTiming);
                cudaEventCreateWithFlags(&evPre[i], cudaEventDisableTiming);
                cudaEventCreateWithFlags(&evS[i], cudaEventDisableTiming);
            }
            cudaEventCreateWithFlags(&evJ, cudaEventDisableTiming);
            s_init = true;
        }

        size_t grpBytes = (size_t)N * 16 * sizeof(unsigned long long); // 64MB
        int sBlocks = (N + 511) / 512;
        int fBlocks = (N + 63) / 64;

        // Capture fork: s2 waits an origin-stream event before its first op.
        cudaEventRecord(evRoot, 0);
        cudaStreamWaitEvent(s2, evRoot, 0);

        // True overlap: evPre[g] (recorded right before sc(g) launches, i.e.
        // fires when ms(g) is done) gates ms(g+1) on s2 -> ms(g+1) ∥ sc(g).
        //   s2:  ms(0) | ms(1)∥sc(0) | ms(2)∥sc(1) | ms(3)∥sc(2)
        //   0 :        sc(0)   sc(1)   sc(2)   sc(3)
        //   s1:              fin(0)  fin(1)  fin(2)  fin(3)
        for (int g = 0; g < 4; ++g) {
            unsigned long long* acc_g =
                reinterpret_cast<unsigned long long*>(accp + (size_t)g * grpBytes);

            if (g == 0) {
                cudaMemsetAsync(accp, 0, grpBytes, s2);
                cudaEventRecord(evM[0], s2);
            }
            cudaStreamWaitEvent(0, evM[g], 0);
            cudaEventRecord(evPre[g], 0);            // fires as sc(g) starts
            if (g + 1 < 4) {
                cudaStreamWaitEvent(s2, evPre[g], 0);
                cudaMemsetAsync(accp + (size_t)(g + 1) * grpBytes, 0, grpBytes, s2);
                cudaEventRecord(evM[g + 1], s2);
            }
            scatter16_kernel<<<sBlocks, 256, 0, 0>>>(src, index, N, g * 16, acc_g);
            cudaEventRecord(evS[g], 0);

            cudaStreamWaitEvent(s1, evS[g], 0);
            finalize16_kernel<<<fBlocks, 256, 0, s1>>>(
                src, out, arg, N, writeArg, g * 16, acc_g);
        }
        cudaEventRecord(evJ, s1);
        cudaStreamWaitEvent(0, evJ, 0);
    } else {
        cudaMemsetAsync(accp, 0, cn * sizeof(unsigned long long), 0);
        int threads = 256;
        scatter_gen_kernel<<<(N + threads - 1) / threads, threads>>>(src, index, C, N);
        long long total = (long long)C * N;
        finalize_gen_kernel<<<(int)((total + threads - 1) / threads), threads>>>(
            src, out, arg, C, N, writeArg);
    }
}

// round 14
// speedup vs baseline: 1.2840x; 1.2840x over previous
#include <cuda_runtime.h>
#include <cstdint>

// Scratch: 4 channel-groups, each acc_g[k*16 + cc] packed
// (sortable_value:32 | (N-j):32). Group footprint = N*16*8B = 64MB (L2-resident).
__device__ unsigned long long g_acc[32000000];

__device__ __forceinline__ unsigned f2sort(float f) {
    unsigned u = __float_as_uint(f);
    return (u & 0x80000000u) ? ~u : (u | 0x80000000u);
}
__device__ __forceinline__ float sort2f(unsigned s) {
    unsigned u = (s & 0x80000000u) ? (s ^ 0x80000000u) : ~s;
    return __uint_as_float(u);
}

// -------------------- Pass 1: scatter + fused next-group zeroing --------------------
// Scatter work: 4 consecutive points x 8 channels per thread (LDG.128 loads,
// contiguous REDG.64 bursts). Then all threads zero a grid-strided slice of the
// NEXT group's scratch with __stcs (evict-first: doesn't pollute the hot set).
// Kernel-boundary ordering guarantees the zeroes land before scatter(g+1).
__global__ void scatter16_kernel(const float* __restrict__ src,
                                 const int* __restrict__ index,
                                 int N, int c0,
                                 unsigned long long* __restrict__ acc,
                                 longlong2* __restrict__ zeroDst) {
    int t    = threadIdx.x;
    int half = t & 1;
    int g    = t >> 1;
    int j0   = blockIdx.x * 512 + g * 4;
    int ch0 = c0 + half * 8;
    int cc0 = half * 8;

    if (j0 + 4 <= N) {
        int4 idx4 = __ldcs(reinterpret_cast<const int4*>(index + j0));
        float4 v[8];
#pragma unroll
        for (int c = 0; c < 8; ++c)
            v[c] = __ldcs(reinterpret_cast<const float4*>(
                src + (size_t)(ch0 + c) * N + j0));

        int kk[4] = {idx4.x, idx4.y, idx4.z, idx4.w};
#pragma unroll
        for (int i = 0; i < 4; ++i) {
            unsigned long long lowkey = (unsigned)(N - (j0 + i));
            unsigned long long* ap = acc + (size_t)kk[i] * 16 + cc0;
#pragma unroll
            for (int c = 0; c < 8; ++c) {
                float fv = (i == 0) ? v[c].x : (i == 1) ? v[c].y
                                             : (i == 2) ? v[c].z : v[c].w;
                unsigned long long p =
                    ((unsigned long long)f2sort(fv) << 32) | lowkey;
                atomicMax(ap + c, p);
            }
        }
    } else if (j0 < N) {
        for (int i = 0; i < 4 && j0 + i < N; ++i) {
            int j = j0 + i;
            int k = __ldcs(index + j);
            unsigned long long lowkey = (unsigned)(N - j);
            unsigned long long* ap = acc + (size_t)k * 16 + cc0;
#pragma unroll
            for (int c = 0; c < 8; ++c) {
                float fv = __ldcs(src + (size_t)(ch0 + c) * N + j);
                unsigned long long p =
                    ((unsigned long long)f2sort(fv) << 32) | lowkey;
                atomicMax(ap + c, p);
            }
        }
    }

    // Fused zeroing of the next group's scratch (all threads participate).
    if (zeroDst) {
        longlong2 zz; zz.x = 0; zz.y = 0;
        long long total2 = (long long)N * 8;          // ll2 count (N*16 u64 / 2)
        long long stride = (long long)gridDim.x * blockDim.x;
        for (long long i = (long long)blockIdx.x * blockDim.x + t;
             i < total2; i += stride)
            __stcs(zeroDst + i, zz);
    }
}

// -------------------- Pass 2: per-group finalize (16 channels) --------------------
__global__ void finalize16_kernel(const float* __restrict__ src,
                                  float* __restrict__ out,
                                  float* __restrict__ arg,
                                  int N, int writeArg, int c0,
                                  const unsigned long long* __restrict__ acc) {
    __shared__ __align__(16) float s_val[16][68];
    __shared__ __align__(16) float s_arg[16][68];
    int k0  = blockIdx.x * 64;
    int tid = threadIdx.x;

    if (k0 + 64 <= N) {
        const longlong2* accv =
            reinterpret_cast<const longlong2*>(acc + (size_t)k0 * 16);
#pragma unroll
        for (int i = 0; i < 2; ++i) {
            int idx2 = i * 256 + tid;          // 0..511 ll2 in tile
            longlong2 p2 = __ldcs(accv + idx2);
            int e  = idx2 * 2;                  // element index kk*16+cc
            int kk = e >> 4;
            int cc = e & 15;
            {
                unsigned long long p = (unsigned long long)p2.x;
                unsigned low = (unsigned)p, hi = (unsigned)(p >> 32);
                s_val[cc][kk] = low ? sort2f(hi) : __int_as_float(0xff800000);
                s_arg[cc][kk] = (float)(low ? (N - (int)low) : N);
            }
            {
                unsigned long long p = (unsigned long long)p2.y;
                unsigned low = (unsigned)p, hi = (unsigned)(p >> 32);
                s_val[cc + 1][kk] = low ? sort2f(hi) : __int_as_float(0xff800000);
                s_arg[cc + 1][kk] = (float)(low ? (N - (int)low) : N);
            }
        }
        __syncthreads();

        float fN = (float)N;
        int c  = tid >> 4;            // 0..15
        int kk = (tid & 15) * 4;      // 0..60
        size_t gidx = (size_t)(c0 + c) * N + (k0 + kk);
        float4 sv = __ldcs(reinterpret_cast<const float4*>(src + gidx));
        float4 sg = *reinterpret_cast<const float4*>(&s_val[c][kk]);
        float4 sa = *reinterpret_cast<const float4*>(&s_arg[c][kk]);
        float4 ov, av;
        ov.x = fmaxf(sv.x, sg.x); av.x = (sg.x >= sv.x) ? sa.x : fN;
        ov.y = fmaxf(sv.y, sg.y); av.y = (sg.y >= sv.y) ? sa.y : fN;
        ov.z = fmaxf(sv.z, sg.z); av.z = (sg.z >= sv.z) ? sa.z : fN;
        ov.w = fmaxf(sv.w, sg.w); av.w = (sg.w >= sv.w) ? sa.w : fN;
        __stcs(reinterpret_cast<float4*>(out + gidx), ov);
        if (writeArg) __stcs(reinterpret_cast<float4*>(arg + gidx), av);
    } else {
        for (int e = tid; e < 64 * 16; e += blockDim.x) {
            int kk = e >> 4;
            int cc = e & 15;
            int k  = k0 + kk;
            float val = __int_as_float(0xff800000);
            int a = N;
            if (k < N) {
                unsigned long long p = acc[(size_t)k * 16 + cc];
                unsigned low = (unsigned)p, hi = (unsigned)(p >> 32);
                if (low) { val = sort2f(hi); a = N - (int)low; }
            }
            s_val[cc][kk] = val;
            s_arg[cc][kk] = (float)a;
        }
        __syncthreads();
        for (int e = tid; e < 16 * 64; e += blockDim.x) {
            int c  = e >> 6;
            int kk = e & 63;
            int k  = k0 + kk;
            if (k < N) {
                size_t idx = (size_t)(c0 + c) * N + k;
                float sv  = src[idx];
                float seg = s_val[c][kk];
                out[idx] = fmaxf(sv, seg);
                if (writeArg) arg[idx] = (seg >= sv) ? s_arg[c][kk] : (float)N;
            }
        }
    }
}

// -------------------- Generic fallback (C != 64) --------------------
__global__ void scatter_gen_kernel(const float* __restrict__ src,
                                   const int* __restrict__ index,
                                   int C, int N) {
    int j = blockIdx.x * blockDim.x + threadIdx.x;
    if (j >= N) return;
    int k = index[j];
    unsigned long long* accp = g_acc + (size_t)k * C;
    unsigned lowkey = (unsigned)(N - j);
    for (int c = 0; c < C; ++c) {
        float v = __ldg(src + (size_t)c * N + j);
        unsigned long long p =
            ((unsigned long long)f2sort(v) << 32) | (unsigned long long)lowkey;
        atomicMax(accp + c, p);
    }
}

__global__ void finalize_gen_kernel(const float* __restrict__ src,
                                    float* __restrict__ out,
                                    float* __restrict__ arg,
                                    int C, int N, int writeArg) {
    long long t = (long long)blockIdx.x * blockDim.x + threadIdx.x;
    long long total = (long long)C * N;
    if (t >= total) return;
    int c = (int)(t / N);
    int k = (int)(t % N);
    unsigned long long p = g_acc[(size_t)k * C + c];
    unsigned low = (unsigned)p, hi = (unsigned)(p >> 32);
    float seg = low ? sort2f(hi) : __int_as_float(0xff800000);
    int   a   = low ? (N - (int)low) : N;
    float sv = src[t];
    out[t] = fmaxf(sv, seg);
    if (writeArg) arg[t] = (float)((seg >= sv) ? a : N);
}

extern "C" void kernel_launch(void* const* d_in, const int* in_sizes, int n_in,
                              void* d_out, int out_size) {
    const float* src   = (const float*)d_in[0];
    const int*   index = (const int*)d_in[1];   // JAX x64-disabled: int32

    int N = in_sizes[1];
    int C = (N > 0) ? (in_sizes[0] / N) : 0;
    if (N <= 0 || C <= 0) return;

    size_t cn = (size_t)C * (size_t)N;

    unsigned char* accp = nullptr;
    cudaGetSymbolAddress((void**)&accp, g_acc);

    float* out = (float*)d_out;
    int writeArg = ((size_t)out_size >= 2 * cn) ? 1 : 0;
    float* arg = out + cn;

    if (C == 64) {
        static bool s_init = false;
        static cudaStream_t s1;
        static cudaEvent_t evS[4], evJ;
        if (!s_init) {
            cudaStreamCreateWithFlags(&s1, cudaStreamNonBlocking);
            for (int i = 0; i < 4; ++i)
                cudaEventCreateWithFlags(&evS[i], cudaEventDisableTiming);
            cudaEventCreateWithFlags(&evJ, cudaEventDisableTiming);
            s_init = true;
        }

        size_t grpBytes = (size_t)N * 16 * sizeof(unsigned long long); // 64MB
        int sBlocks = (N + 511) / 512;
        int fBlocks = (N + 63) / 64;

        // ms0, then sc(g) zeroes group g+1 internally (stcs, evict-first).
        //   0 : ms0  sc0(+z1)  sc1(+z2)  sc2(+z3)  sc3
        //   s1:          fin0      fin1      fin2     fin3
        cudaMemsetAsync(accp, 0, grpBytes, 0);
        for (int g = 0; g < 4; ++g) {
            unsigned long long* acc_g =
                reinterpret_cast<unsigned long long*>(accp + (size_t)g * grpBytes);
            longlong2* zeroDst = (g + 1 < 4)
                ? reinterpret_cast<longlong2*>(accp + (size_t)(g + 1) * grpBytes)
                : nullptr;
            scatter16_kernel<<<sBlocks, 256, 0, 0>>>(
                src, index, N, g * 16, acc_g, zeroDst);
            cudaEventRecord(evS[g], 0);
            cudaStreamWaitEvent(s1, evS[g], 0);
            finalize16_kernel<<<fBlocks, 256, 0, s1>>>(
                src, out, arg, N, writeArg, g * 16, acc_g);
        }
        cudaEventRecord(evJ, s1);
        cudaStreamWaitEvent(0, evJ, 0);
    } else {
        cudaMemsetAsync(accp, 0, cn * sizeof(unsigned long long), 0);
        int threads = 256;
        scatter_gen_kernel<<<(N + threads - 1) / threads, threads>>>(src, index, C, N);
        long long total = (long long)C * N;
        finalize_gen_kernel<<<(int)((total + threads - 1) / threads), threads>>>(
            src, out, arg, C, N, writeArg);
    }
}

// round 15
// speedup vs baseline: 1.9534x; 1.5213x over previous
#include <cuda_runtime.h>
#include <cstdint>

// Scratch: 4 channel-groups, each acc_g[k*16 + cc] packed
// (sortable_value:32 | (N-j):32). Group footprint = N*16*8B = 64MB (L2-resident).
__device__ unsigned long long g_acc[32000000];

__device__ __forceinline__ unsigned f2sort(float f) {
    unsigned u = __float_as_uint(f);
    return (u & 0x80000000u) ? ~u : (u | 0x80000000u);
}
__device__ __forceinline__ float sort2f(unsigned s) {
    unsigned u = (s & 0x80000000u) ? (s ^ 0x80000000u) : ~s;
    return __uint_as_float(u);
}

// -------------------- Pass 1: scatter with LINE-COALESCED atomics --------------------
// Block (256 thr) handles 512 points x 16 channels. Stage src tile + indices in
// smem (coalesced), then each warp emits REDG.64 bursts where lanes 0-15 cover
// the 16 channels of ONE point (one contiguous 128B line) and lanes 16-31 the
// next point: 2 lines per warp-instruction instead of 32.
__global__ void scatter16_kernel(const float* __restrict__ src,
                                 const int* __restrict__ index,
                                 int N, int c0,
                                 unsigned long long* __restrict__ acc) {
    __shared__ float s_src[16][513];
    __shared__ __align__(16) int s_idx[512];
    int tid = threadIdx.x;
    int j0  = blockIdx.x * 512;
    int nPts = N - j0; if (nPts > 512) nPts = 512;

    // stage indices (int4 coalesced)
    if (tid < 128) {
        int base = tid * 4;
        int4 i4;
        if (j0 + base + 3 < N) {
            i4 = __ldcs(reinterpret_cast<const int4*>(index + j0 + base));
        } else {
            i4.x = (j0 + base + 0 < N) ? index[j0 + base + 0] : 0;
            i4.y = (j0 + base + 1 < N) ? index[j0 + base + 1] : 0;
            i4.z = (j0 + base + 2 < N) ? index[j0 + base + 2] : 0;
            i4.w = (j0 + base + 3 < N) ? index[j0 + base + 3] : 0;
        }
        *reinterpret_cast<int4*>(&s_idx[base]) = i4;
    }

    // stage src tile: 16 rows x 128 float4 (coalesced LDG.128 per row)
#pragma unroll
    for (int e = tid; e < 16 * 128; e += 256) {
        int row  = e >> 7;
        int col4 = e & 127;
        int j = j0 + col4 * 4;
        float4 v;
        if (j + 3 < N) {
            v = __ldcs(reinterpret_cast<const float4*>(
                src + (size_t)(c0 + row) * N + j));
        } else {
            const float* sp = src + (size_t)(c0 + row) * N;
            v.x = (j + 0 < N) ? sp[j + 0] : 0.f;
            v.y = (j + 1 < N) ? sp[j + 1] : 0.f;
            v.z = (j + 2 < N) ? sp[j + 2] : 0.f;
            v.w = (j + 3 < N) ? sp[j + 3] : 0.f;
        }
        s_src[row][col4 * 4 + 0] = v.x;
        s_src[row][col4 * 4 + 1] = v.y;
        s_src[row][col4 * 4 + 2] = v.z;
        s_src[row][col4 * 4 + 3] = v.w;
    }
    __syncthreads();

    // atomic phase: 8 warps x 64 points each; 2 points per instruction
    int w = tid >> 5;
    int L = tid & 31;
    int c = L & 15;
    int sub = L >> 4;                 // 0 or 1
#pragma unroll 4
    for (int i = 0; i < 32; ++i) {
        int p = w * 64 + 2 * i + sub;
        if (p < nPts) {
            int k = s_idx[p];
            float fv = s_src[c][p];
            unsigned long long pk =
                ((unsigned long long)f2sort(fv) << 32) |
                (unsigned long long)(unsigned)(N - (j0 + p));
            atomicMax(acc + (size_t)k * 16 + c, pk);
        }
    }
}

// -------------------- Pass 2: per-group finalize (16 channels) --------------------
__global__ void finalize16_kernel(const float* __restrict__ src,
                                  float* __restrict__ out,
                                  float* __restrict__ arg,
                                  int N, int writeArg, int c0,
                                  const unsigned long long* __restrict__ acc) {
    __shared__ __align__(16) float s_val[16][68];
    __shared__ __align__(16) float s_arg[16][68];
    int k0  = blockIdx.x * 64;
    int tid = threadIdx.x;

    if (k0 + 64 <= N) {
        const longlong2* accv =
            reinterpret_cast<const longlong2*>(acc + (size_t)k0 * 16);
#pragma unroll
        for (int i = 0; i < 2; ++i) {
            int idx2 = i * 256 + tid;
            longlong2 p2 = __ldcs(accv + idx2);
            int e  = idx2 * 2;
            int kk = e >> 4;
            int cc = e & 15;
            {
                unsigned long long p = (unsigned long long)p2.x;
                unsigned low = (unsigned)p, hi = (unsigned)(p >> 32);
                s_val[cc][kk] = low ? sort2f(hi) : __int_as_float(0xff800000);
                s_arg[cc][kk] = (float)(low ? (N - (int)low) : N);
            }
            {
                unsigned long long p = (unsigned long long)p2.y;
                unsigned low = (unsigned)p, hi = (unsigned)(p >> 32);
                s_val[cc + 1][kk] = low ? sort2f(hi) : __int_as_float(0xff800000);
                s_arg[cc + 1][kk] = (float)(low ? (N - (int)low) : N);
            }
        }
        __syncthreads();

        float fN = (float)N;
        int c  = tid >> 4;
        int kk = (tid & 15) * 4;
        size_t gidx = (size_t)(c0 + c) * N + (k0 + kk);
        float4 sv = __ldcs(reinterpret_cast<const float4*>(src + gidx));
        float4 sg = *reinterpret_cast<const float4*>(&s_val[c][kk]);
        float4 sa = *reinterpret_cast<const float4*>(&s_arg[c][kk]);
        float4 ov, av;
        ov.x = fmaxf(sv.x, sg.x); av.x = (sg.x >= sv.x) ? sa.x : fN;
        ov.y = fmaxf(sv.y, sg.y); av.y = (sg.y >= sv.y) ? sa.y : fN;
        ov.z = fmaxf(sv.z, sg.z); av.z = (sg.z >= sv.z) ? sa.z : fN;
        ov.w = fmaxf(sv.w, sg.w); av.w = (sg.w >= sv.w) ? sa.w : fN;
        __stcs(reinterpret_cast<float4*>(out + gidx), ov);
        if (writeArg) __stcs(reinterpret_cast<float4*>(arg + gidx), av);
    } else {
        for (int e = tid; e < 64 * 16; e += blockDim.x) {
            int kk = e >> 4;
            int cc = e & 15;
            int k  = k0 + kk;
            float val = __int_as_float(0xff800000);
            int a = N;
            if (k < N) {
                unsigned long long p = acc[(size_t)k * 16 + cc];
                unsigned low = (unsigned)p, hi = (unsigned)(p >> 32);
                if (low) { val = sort2f(hi); a = N - (int)low; }
            }
            s_val[cc][kk] = val;
            s_arg[cc][kk] = (float)a;
        }
        __syncthreads();
        for (int e = tid; e < 16 * 64; e += blockDim.x) {
            int c  = e >> 6;
            int kk = e & 63;
            int k  = k0 + kk;
            if (k < N) {
                size_t idx = (size_t)(c0 + c) * N + k;
                float sv  = src[idx];
                float seg = s_val[c][kk];
                out[idx] = fmaxf(sv, seg);
                if (writeArg) arg[idx] = (seg >= sv) ? s_arg[c][kk] : (float)N;
            }
        }
    }
}

// -------------------- Generic fallback (C != 64) --------------------
__global__ void scatter_gen_kernel(const float* __restrict__ src,
                                   const int* __restrict__ index,
                                   int C, int N) {
    int j = blockIdx.x * blockDim.x + threadIdx.x;
    if (j >= N) return;
    int k = index[j];
    unsigned long long* accp = g_acc + (size_t)k * C;
    unsigned lowkey = (unsigned)(N - j);
    for (int c = 0; c < C; ++c) {
        float v = __ldg(src + (size_t)c * N + j);
        unsigned long long p =
            ((unsigned long long)f2sort(v) << 32) | (unsigned long long)lowkey;
        atomicMax(accp + c, p);
    }
}

__global__ void finalize_gen_kernel(const float* __restrict__ src,
                                    float* __restrict__ out,
                                    float* __restrict__ arg,
                                    int C, int N, int writeArg) {
    long long t = (long long)blockIdx.x * blockDim.x + threadIdx.x;
    long long total = (long long)C * N;
    if (t >= total) return;
    int c = (int)(t / N);
    int k = (int)(t % N);
    unsigned long long p = g_acc[(size_t)k * C + c];
    unsigned low = (unsigned)p, hi = (unsigned)(p >> 32);
    float seg = low ? sort2f(hi) : __int_as_float(0xff800000);
    int   a   = low ? (N - (int)low) : N;
    float sv = src[t];
    out[t] = fmaxf(sv, seg);
    if (writeArg) arg[t] = (float)((seg >= sv) ? a : N);
}

extern "C" void kernel_launch(void* const* d_in, const int* in_sizes, int n_in,
                              void* d_out, int out_size) {
    const float* src   = (const float*)d_in[0];
    const int*   index = (const int*)d_in[1];   // JAX x64-disabled: int32

    int N = in_sizes[1];
    int C = (N > 0) ? (in_sizes[0] / N) : 0;
    if (N <= 0 || C <= 0) return;

    size_t cn = (size_t)C * (size_t)N;

    unsigned char* accp = nullptr;
    cudaGetSymbolAddress((void**)&accp, g_acc);

    float* out = (float*)d_out;
    int writeArg = ((size_t)out_size >= 2 * cn) ? 1 : 0;
    float* arg = out + cn;

    if (C == 64) {
        static bool s_init = false;
        static cudaStream_t s1;
        static cudaEvent_t evS[4], evJ;
        if (!s_init) {
            cudaStreamCreateWithFlags(&s1, cudaStreamNonBlocking);
            for (int i = 0; i < 4; ++i)
                cudaEventCreateWithFlags(&evS[i], cudaEventDisableTiming);
            cudaEventCreateWithFlags(&evJ, cudaEventDisableTiming);
            s_init = true;
        }

        size_t grpBytes = (size_t)N * 16 * sizeof(unsigned long long); // 64MB
        int sBlocks = (N + 511) / 512;
        int fBlocks = (N + 63) / 64;

        // R7 topology (proven): serial ms(g)->sc(g) on stream 0; fin on s1.
        for (int g = 0; g < 4; ++g) {
            unsigned long long* acc_g =
                reinterpret_cast<unsigned long long*>(accp + (size_t)g * grpBytes);
            cudaMemsetAsync(accp + (size_t)g * grpBytes, 0, grpBytes, 0);
            scatter16_kernel<<<sBlocks, 256, 0, 0>>>(src, index, N, g * 16, acc_g);
            cudaEventRecord(evS[g], 0);
            cudaStreamWaitEvent(s1, evS[g], 0);
            finalize16_kernel<<<fBlocks, 256, 0, s1>>>(
                src, out, arg, N, writeArg, g * 16, acc_g);
        }
        cudaEventRecord(evJ, s1);
        cudaStreamWaitEvent(0, evJ, 0);
    } else {
        cudaMemsetAsync(accp, 0, cn * sizeof(unsigned long long), 0);
        int threads = 256;
        scatter_gen_kernel<<<(N + threads - 1) / threads, threads>>>(src, index, C, N);
        long long total = (long long)C * N;
        finalize_gen_kernel<<<(int)((total + threads - 1) / threads), threads>>>(
            src, out, arg, C, N, writeArg);
    }
}